// round 9
// baseline (speedup 1.0000x reference)
#include <cuda_runtime.h>
#include <cstdint>

// Shapes fixed by the problem
#define B_DIM 512
#define T_DIM 400
#define V_DIM 32000
#define ENC_DIM 1024
#define HID_DIM 1024
#define EMB_DIM 512

#define SLICES 2                        // column slices per row
#define SLICE_F (V_DIM / SLICES)        // 16000 floats per slice
#define SLICE_F8 (SLICE_F / 8)          // 2000 float8 per slice
#define NT 256                          // threads per CTA
#define FULL_ITERS (SLICE_F8 / NT)      // 7 full passes
#define TAIL (SLICE_F8 - FULL_ITERS * NT)   // 208 threads in tail

#define BM_WORDS (SLICE_F / 32)         // 500 bitmap words
#define HASH_SZ  1024                   // power of two, >= 400 worst-case entries
#define HASH_MASK (HASH_SZ - 1)
#define EMPTY_KEY 0xFFFFFFFFu

// sm_103a: L2 eviction hints require 256-bit (.v8.b32) accesses.
struct F8 { uint32_t r[8]; };

__device__ __forceinline__ F8 ldg256_evict_last(const float* p) {
    F8 v;
    asm volatile("ld.global.nc.L2::evict_last.v8.b32 {%0,%1,%2,%3,%4,%5,%6,%7}, [%8];"
                 : "=r"(v.r[0]), "=r"(v.r[1]), "=r"(v.r[2]), "=r"(v.r[3]),
                   "=r"(v.r[4]), "=r"(v.r[5]), "=r"(v.r[6]), "=r"(v.r[7])
                 : "l"(p));
    return v;
}
__device__ __forceinline__ void stg256_evict_first(float* p, const F8& v) {
    asm volatile("st.global.L2::evict_first.v8.b32 [%0], {%1,%2,%3,%4,%5,%6,%7,%8};"
                 :: "l"(p),
                    "r"(v.r[0]), "r"(v.r[1]), "r"(v.r[2]), "r"(v.r[3]),
                    "r"(v.r[4]), "r"(v.r[5]), "r"(v.r[6]), "r"(v.r[7])
                 : "memory");
}

// ---------------------------------------------------------------------------
// Single fused kernel, 1024 CTAs. Each CTA owns one (row, slice):
//   1. redundantly computes the row's p_gen (2x redundancy, L2-amortized)
//   2. builds a smem bitmap + hash of this slice's scatter contributions
//      (local_idx -> sum of (1-pg)*attn over duplicate src_ids)
//   3. streams its vocab slice with 256-bit accesses, fusing the scatter
//      adds into the store:  out = pg*vocab (+ contribution on bitmap hit)
// NO global atomics, no post-stream phase -> no DRAM line refetch.
// ---------------------------------------------------------------------------
__global__ __launch_bounds__(NT)
void pointer_generator_fused(
    const float* __restrict__ vocab_dist,   // [B, V]
    const float* __restrict__ attn_dist,    // [B, T]
    const float* __restrict__ context,      // [B, ENC]
    const float* __restrict__ state,        // [B, HID]
    const float* __restrict__ emb,          // [B, EMB]
    const int*   __restrict__ src_ids,      // [B, T]
    const int*   __restrict__ vocab_size_p, // scalar
    const float* __restrict__ w_c,          // [ENC]
    const float* __restrict__ w_s,          // [HID]
    const float* __restrict__ w_y,          // [EMB]
    const float* __restrict__ b_p,          // [1]
    float*       __restrict__ out)          // [B, V]
{
    const int bid   = blockIdx.x;
    const int row   = bid >> 1;      // SLICES == 2
    const int slice = bid & 1;
    const int tid   = threadIdx.x;

    __shared__ uint32_t s_bitmap[BM_WORDS];
    __shared__ uint32_t s_hkey[HASH_SZ];
    __shared__ float    s_hval[HASH_SZ];
    __shared__ float    s_partial[NT / 32];

    // ---- zero scatter structures (overlaps with pgen loads below in issue order)
    #pragma unroll
    for (int i = tid; i < BM_WORDS; i += NT) s_bitmap[i] = 0u;
    #pragma unroll
    for (int i = tid; i < HASH_SZ; i += NT) { s_hkey[i] = EMPTY_KEY; s_hval[i] = 0.0f; }

    // ---------------- Phase 1: p_gen (2x redundant, L2-amortized) ----------------
    float acc = 0.0f;
    {
        const float4 a = reinterpret_cast<const float4*>(context + (size_t)row * ENC_DIM)[tid];
        const float4 w = reinterpret_cast<const float4*>(w_c)[tid];
        acc += a.x * w.x + a.y * w.y + a.z * w.z + a.w * w.w;
    }
    {
        const float4 a = reinterpret_cast<const float4*>(state + (size_t)row * HID_DIM)[tid];
        const float4 w = reinterpret_cast<const float4*>(w_s)[tid];
        acc += a.x * w.x + a.y * w.y + a.z * w.z + a.w * w.w;
    }
    if (tid < EMB_DIM / 4) {
        const float4 a = reinterpret_cast<const float4*>(emb + (size_t)row * EMB_DIM)[tid];
        const float4 w = reinterpret_cast<const float4*>(w_y)[tid];
        acc += a.x * w.x + a.y * w.y + a.z * w.z + a.w * w.w;
    }

    #pragma unroll
    for (int off = 16; off > 0; off >>= 1)
        acc += __shfl_down_sync(0xffffffffu, acc, off);

    const int lane = tid & 31;
    const int wid  = tid >> 5;
    if (lane == 0) s_partial[wid] = acc;
    __syncthreads();

    float total = b_p[0];
    #pragma unroll
    for (int i = 0; i < NT / 32; i++) total += s_partial[i];
    const float pg = 1.0f / (1.0f + __expf(-total));
    const float pc = 1.0f - pg;

    // ---------------- Phase 2: build bitmap + hash of scatter contributions ----
    {
        const int vsz = *vocab_size_p;
        const int lo  = slice * SLICE_F;
        const int hi  = lo + SLICE_F;
        const int*   ids = src_ids   + (size_t)row * T_DIM;
        const float* at  = attn_dist + (size_t)row * T_DIM;

        #pragma unroll
        for (int t = tid; t < T_DIM; t += NT) {
            const int id = ids[t];
            if (id < vsz && id >= lo && id < hi) {
                const uint32_t local = (uint32_t)(id - lo);
                const float    v     = pc * at[t];
                atomicOr(&s_bitmap[local >> 5], 1u << (local & 31));
                uint32_t h = (local * 2654435761u) >> 22;   // top 10 bits
                for (;;) {
                    uint32_t prev = atomicCAS(&s_hkey[h], EMPTY_KEY, local);
                    if (prev == EMPTY_KEY || prev == local) {
                        atomicAdd(&s_hval[h], v);
                        break;
                    }
                    h = (h + 1) & HASH_MASK;
                }
            }
        }
    }
    __syncthreads();

    // ---------------- Phase 3: stream vocab slice, fuse adds into the store ----
    const float* vbase = vocab_dist + (size_t)row * V_DIM + slice * SLICE_F;
    float*       obase = out        + (size_t)row * V_DIM + slice * SLICE_F;

    #pragma unroll 2
    for (int k = 0; k < FULL_ITERS; k++) {
        const int idx = (tid + k * NT) * 8;           // element offset in slice
        F8 x = ldg256_evict_last(vbase + idx);
        #pragma unroll
        for (int j = 0; j < 8; j++)
            x.r[j] = __float_as_uint(pg * __uint_as_float(x.r[j]));
        uint32_t bits = (s_bitmap[idx >> 5] >> (idx & 31)) & 0xFFu;
        while (bits) {
            const int j = __ffs(bits) - 1;
            bits &= bits - 1;
            const uint32_t local = (uint32_t)(idx + j);
            uint32_t h = (local * 2654435761u) >> 22;
            while (s_hkey[h] != local) h = (h + 1) & HASH_MASK;
            x.r[j] = __float_as_uint(__uint_as_float(x.r[j]) + s_hval[h]);
        }
        stg256_evict_first(obase + idx, x);
    }
    if (tid < TAIL) {
        const int idx = (tid + FULL_ITERS * NT) * 8;
        F8 x = ldg256_evict_last(vbase + idx);
        #pragma unroll
        for (int j = 0; j < 8; j++)
            x.r[j] = __float_as_uint(pg * __uint_as_float(x.r[j]));
        uint32_t bits = (s_bitmap[idx >> 5] >> (idx & 31)) & 0xFFu;
        while (bits) {
            const int j = __ffs(bits) - 1;
            bits &= bits - 1;
            const uint32_t local = (uint32_t)(idx + j);
            uint32_t h = (local * 2654435761u) >> 22;
            while (s_hkey[h] != local) h = (h + 1) & HASH_MASK;
            x.r[j] = __float_as_uint(__uint_as_float(x.r[j]) + s_hval[h]);
        }
        stg256_evict_first(obase + idx, x);
    }
}

extern "C" void kernel_launch(void* const* d_in, const int* in_sizes, int n_in,
                              void* d_out, int out_size) {
    const float* vocab_dist = (const float*)d_in[0];
    const float* attn_dist  = (const float*)d_in[1];
    const float* context    = (const float*)d_in[2];
    const float* state      = (const float*)d_in[3];
    const float* emb        = (const float*)d_in[4];
    const int*   src_ids    = (const int*)d_in[5];
    const int*   vocab_size = (const int*)d_in[6];
    const float* w_c        = (const float*)d_in[7];
    const float* w_s        = (const float*)d_in[8];
    const float* w_y        = (const float*)d_in[9];
    const float* b          = (const float*)d_in[10];
    float*       out        = (float*)d_out;

    pointer_generator_fused<<<B_DIM * SLICES, NT>>>(
        vocab_dist, attn_dist, context, state, emb, src_ids, vocab_size,
        w_c, w_s, w_y, b, out);
}

// round 10
// speedup vs baseline: 1.1579x; 1.1579x over previous
#include <cuda_runtime.h>
#include <cstdint>

// Shapes fixed by the problem
#define B_DIM 512
#define T_DIM 400
#define V_DIM 32000
#define ENC_DIM 1024
#define HID_DIM 1024
#define EMB_DIM 512

#define SLICES 2                        // column slices per row
#define SLICE_F (V_DIM / SLICES)        // 16000 floats per slice
#define SLICE_F8 (SLICE_F / 8)          // 2000 float8 per slice
#define NT 256                          // threads per CTA
#define FULL_ITERS (SLICE_F8 / NT)      // 7 full passes (k=0 prefetched)
#define TAIL (SLICE_F8 - FULL_ITERS * NT)   // 208 threads in tail

// sm_103a: L2 eviction hints require 256-bit (.v8.b32) accesses.
struct F8 { uint32_t r[8]; };

__device__ __forceinline__ F8 ldg256_evict_last(const float* p) {
    F8 v;
    asm volatile("ld.global.nc.L2::evict_last.v8.b32 {%0,%1,%2,%3,%4,%5,%6,%7}, [%8];"
                 : "=r"(v.r[0]), "=r"(v.r[1]), "=r"(v.r[2]), "=r"(v.r[3]),
                   "=r"(v.r[4]), "=r"(v.r[5]), "=r"(v.r[6]), "=r"(v.r[7])
                 : "l"(p));
    return v;
}
__device__ __forceinline__ void stg256_evict_first(float* p, const F8& v) {
    asm volatile("st.global.L2::evict_first.v8.b32 [%0], {%1,%2,%3,%4,%5,%6,%7,%8};"
                 :: "l"(p),
                    "r"(v.r[0]), "r"(v.r[1]), "r"(v.r[2]), "r"(v.r[3]),
                    "r"(v.r[4]), "r"(v.r[5]), "r"(v.r[6]), "r"(v.r[7])
                 : "memory");
}
__device__ __forceinline__ void cp_async_cg16(uint32_t saddr, const void* gptr) {
    asm volatile("cp.async.cg.shared.global [%0], [%1], 16;"
                 :: "r"(saddr), "l"(gptr));
}
__device__ __forceinline__ uint32_t smem_u32(const void* p) {
    uint32_t a;
    asm("{ .reg .u64 t; cvta.to.shared.u64 t, %1; cvt.u32.u64 %0, t; }" : "=r"(a) : "l"(p));
    return a;
}

// ---------------------------------------------------------------------------
// Single fused kernel, 1024 CTAs, one fully-resident wave (8 CTAs/SM).
// Each CTA owns one (row, slice). cp.async prefetch hides the two
// once-per-kernel phase bubbles (scatter-input loads; first stream chunk)
// behind the pgen reduction.
// ---------------------------------------------------------------------------
__global__ __launch_bounds__(NT, 8)
void pointer_generator_fused(
    const float* __restrict__ vocab_dist,   // [B, V]
    const float* __restrict__ attn_dist,    // [B, T]
    const float* __restrict__ context,      // [B, ENC]
    const float* __restrict__ state,        // [B, HID]
    const float* __restrict__ emb,          // [B, EMB]
    const int*   __restrict__ src_ids,      // [B, T]
    const int*   __restrict__ vocab_size_p, // scalar
    const float* __restrict__ w_c,          // [ENC]
    const float* __restrict__ w_s,          // [HID]
    const float* __restrict__ w_y,          // [EMB]
    const float* __restrict__ b_p,          // [1]
    float*       __restrict__ out)          // [B, V]
{
    const int bid   = blockIdx.x;
    const int row   = bid >> 1;      // SLICES == 2
    const int slice = bid & 1;
    const int tid   = threadIdx.x;

    __shared__ float    s_chunk0[NT * 8];   // 8 KB: stream chunk k=0
    __shared__ int      s_ids[T_DIM];       // 1.6 KB
    __shared__ float    s_at[T_DIM];        // 1.6 KB
    __shared__ float    s_partial[NT / 32];

    const float* vbase = vocab_dist + (size_t)row * V_DIM + slice * SLICE_F;
    float*       obase = out        + (size_t)row * V_DIM + slice * SLICE_F;

    // ---- Prefetch group A: scatter inputs (ids + attn), 100 x 16B each ----
    if (tid < T_DIM / 4) {
        cp_async_cg16(smem_u32(&s_ids[tid * 4]), src_ids + (size_t)row * T_DIM + tid * 4);
    } else if (tid >= 128 && tid < 128 + T_DIM / 4) {
        const int i = tid - 128;
        cp_async_cg16(smem_u32(&s_at[i * 4]), attn_dist + (size_t)row * T_DIM + i * 4);
    }
    asm volatile("cp.async.commit_group;");

    // ---- Prefetch group B: stream chunk 0 (own 32 B per thread) ----
    {
        const uint32_t sa = smem_u32(&s_chunk0[tid * 8]);
        cp_async_cg16(sa,      vbase + tid * 8);
        cp_async_cg16(sa + 16, vbase + tid * 8 + 4);
    }
    asm volatile("cp.async.commit_group;");

    // ---------------- Phase 1: p_gen (2x redundant, L2-amortized) ----------------
    float acc = 0.0f;
    {
        const float4 a = reinterpret_cast<const float4*>(context + (size_t)row * ENC_DIM)[tid];
        const float4 w = reinterpret_cast<const float4*>(w_c)[tid];
        acc += a.x * w.x + a.y * w.y + a.z * w.z + a.w * w.w;
    }
    {
        const float4 a = reinterpret_cast<const float4*>(state + (size_t)row * HID_DIM)[tid];
        const float4 w = reinterpret_cast<const float4*>(w_s)[tid];
        acc += a.x * w.x + a.y * w.y + a.z * w.z + a.w * w.w;
    }
    if (tid < EMB_DIM / 4) {
        const float4 a = reinterpret_cast<const float4*>(emb + (size_t)row * EMB_DIM)[tid];
        const float4 w = reinterpret_cast<const float4*>(w_y)[tid];
        acc += a.x * w.x + a.y * w.y + a.z * w.z + a.w * w.w;
    }

    #pragma unroll
    for (int off = 16; off > 0; off >>= 1)
        acc += __shfl_down_sync(0xffffffffu, acc, off);

    const int lane = tid & 31;
    const int wid  = tid >> 5;
    if (lane == 0) s_partial[wid] = acc;

    // Group A must be complete before the barrier so phase 3's cross-thread
    // reads of s_ids/s_at are safe.
    asm volatile("cp.async.wait_group 1;");
    __syncthreads();

    float total = b_p[0];
    #pragma unroll
    for (int i = 0; i < NT / 32; i++) total += s_partial[i];
    const float pg = 1.0f / (1.0f + __expf(-total));
    const float pc = 1.0f - pg;

    // ---------------- Phase 2: stream the vocab slice (256-bit) ----------------
    // k = 0 from the smem prefetch (own data: wait_group 0, no barrier needed).
    asm volatile("cp.async.wait_group 0;");
    {
        F8 x;
        const float4 a = reinterpret_cast<const float4*>(&s_chunk0[tid * 8])[0];
        const float4 b = reinterpret_cast<const float4*>(&s_chunk0[tid * 8])[1];
        x.r[0] = __float_as_uint(pg * a.x); x.r[1] = __float_as_uint(pg * a.y);
        x.r[2] = __float_as_uint(pg * a.z); x.r[3] = __float_as_uint(pg * a.w);
        x.r[4] = __float_as_uint(pg * b.x); x.r[5] = __float_as_uint(pg * b.y);
        x.r[6] = __float_as_uint(pg * b.z); x.r[7] = __float_as_uint(pg * b.w);
        stg256_evict_first(obase + tid * 8, x);
    }
    #pragma unroll 2
    for (int k = 1; k < FULL_ITERS; k++) {
        const int idx = (tid + k * NT) * 8;
        F8 x = ldg256_evict_last(vbase + idx);
        #pragma unroll
        for (int j = 0; j < 8; j++)
            x.r[j] = __float_as_uint(pg * __uint_as_float(x.r[j]));
        stg256_evict_first(obase + idx, x);
    }
    if (tid < TAIL) {
        const int idx = (tid + FULL_ITERS * NT) * 8;
        F8 x = ldg256_evict_last(vbase + idx);
        #pragma unroll
        for (int j = 0; j < 8; j++)
            x.r[j] = __float_as_uint(pg * __uint_as_float(x.r[j]));
        stg256_evict_first(obase + idx, x);
    }

    // Block-scope ordering: this CTA's stores visible to this CTA's atomics.
    __syncthreads();

    // ---------------- Phase 3: slice-restricted masked scatter-add ----------------
    const int vsz = *vocab_size_p;
    const int lo  = slice * SLICE_F;
    const int hi  = lo + SLICE_F;

    #pragma unroll
    for (int t = tid; t < T_DIM; t += NT) {
        const int id = s_ids[t];
        if (id < vsz && id >= lo && id < hi) {
            atomicAdd(out + (size_t)row * V_DIM + id, pc * s_at[t]);
        }
    }
}

extern "C" void kernel_launch(void* const* d_in, const int* in_sizes, int n_in,
                              void* d_out, int out_size) {
    const float* vocab_dist = (const float*)d_in[0];
    const float* attn_dist  = (const float*)d_in[1];
    const float* context    = (const float*)d_in[2];
    const float* state      = (const float*)d_in[3];
    const float* emb        = (const float*)d_in[4];
    const int*   src_ids    = (const int*)d_in[5];
    const int*   vocab_size = (const int*)d_in[6];
    const float* w_c        = (const float*)d_in[7];
    const float* w_s        = (const float*)d_in[8];
    const float* w_y        = (const float*)d_in[9];
    const float* b          = (const float*)d_in[10];
    float*       out        = (float*)d_out;

    pointer_generator_fused<<<B_DIM * SLICES, NT>>>(
        vocab_dist, attn_dist, context, state, emb, src_ids, vocab_size,
        w_c, w_s, w_y, b, out);
}